// round 1
// baseline (speedup 1.0000x reference)
#include <cuda_runtime.h>
#include <cstdint>

#define N_NODES 50000
#define D_DIM   128
#define R_REL   4
#define L_LAY   3

// Scratch (static device arrays — no runtime allocation allowed)
__device__ float g_xA[(size_t)N_NODES * D_DIM];
__device__ float g_xB[(size_t)N_NODES * D_DIM];
__device__ float g_h [(size_t)N_NODES * R_REL * D_DIM];

// ---------------------------------------------------------------------------
// Kernel 1: x = emb[node_type]   (one float4 per thread)
// ---------------------------------------------------------------------------
__global__ void embed_kernel(const int* __restrict__ node_type,
                             const float* __restrict__ emb,
                             float* __restrict__ x, int n)
{
    int idx = blockIdx.x * blockDim.x + threadIdx.x;   // over n*32 float4s
    if (idx >= n * 32) return;
    int node = idx >> 5;
    int q    = idx & 31;
    float4 v = reinterpret_cast<const float4*>(emb + (size_t)node_type[node] * D_DIM)[q];
    reinterpret_cast<float4*>(x + (size_t)node * D_DIM)[q] = v;
}

// ---------------------------------------------------------------------------
// Kernel 2: per-relation scatter-add.  One warp per edge, 4 floats per lane,
// vectorized reduction red.global.add.v4.f32 (sm_90+).
// h[dst, r, :] += x[src, :]
// ---------------------------------------------------------------------------
__global__ void scatter_kernel(const int* __restrict__ edge_index,
                               const int* __restrict__ edge_type,
                               const float* __restrict__ x,
                               float* __restrict__ h, int E)
{
    int warp = (blockIdx.x * blockDim.x + threadIdx.x) >> 5;
    int lane = threadIdx.x & 31;
    if (warp >= E) return;
    int src = edge_index[warp];
    int dst = edge_index[E + warp];
    int r   = edge_type[warp];
    float4 v = reinterpret_cast<const float4*>(x + (size_t)src * D_DIM)[lane];
    float* p = h + (size_t)dst * (R_REL * D_DIM) + r * D_DIM + lane * 4;
    asm volatile("red.global.add.v4.f32 [%0], {%1,%2,%3,%4};"
                 :: "l"(p), "f"(v.x), "f"(v.y), "f"(v.z), "f"(v.w) : "memory");
}

// ---------------------------------------------------------------------------
// Kernel 3: fused layer GEMM + bias + leaky_relu.
//   y = leaky_relu( x @ root_l  +  h @ W_l  +  bias_l )
// A1 = x [n,128], B1 = root_l [128,128]; A2 = h [n,512], B2 = W_l [512,128].
// BM=64, BN=128, BK=16; 256 threads; each thread computes 8x4 outputs.
// ---------------------------------------------------------------------------
__global__ __launch_bounds__(256, 4)
void layer_gemm_kernel(const float* __restrict__ x,
                       const float* __restrict__ h,
                       const float* __restrict__ root_l,
                       const float* __restrict__ W_l,
                       const float* __restrict__ bias_l,
                       float* __restrict__ y, int n)
{
    __shared__ float As[16][64];    // transposed: As[k][m]
    __shared__ float Bs[16][128];   // Bs[k][n]

    const int tid  = threadIdx.x;
    const int m0   = blockIdx.x * 64;
    const int trow = tid >> 5;      // 0..7  -> rows trow*8 .. +7
    const int tcol = tid & 31;      // 0..31 -> cols tcol*4 .. +3
    const int arow = tid >> 2;      // 0..63 A-tile row for loads
    const int aq   = tid & 3;       // float4 index within 16-wide k slice

    float acc[8][4];
    #pragma unroll
    for (int i = 0; i < 8; i++)
        #pragma unroll
        for (int j = 0; j < 4; j++) acc[i][j] = 0.f;

    const int grow = m0 + arow;
    const bool a_ok = (grow < n);

    #pragma unroll
    for (int phase = 0; phase < 2; phase++) {
        const float* A   = phase ? h   : x;
        const float* B   = phase ? W_l : root_l;
        const int    K   = phase ? 512 : 128;
        const int    lda = K;

        for (int kk = 0; kk < K; kk += 16) {
            // --- A tile (transposed into As) ---
            float4 av = make_float4(0.f, 0.f, 0.f, 0.f);
            if (a_ok)
                av = *reinterpret_cast<const float4*>(A + (size_t)grow * lda + kk + aq * 4);
            As[aq * 4 + 0][arow] = av.x;
            As[aq * 4 + 1][arow] = av.y;
            As[aq * 4 + 2][arow] = av.z;
            As[aq * 4 + 3][arow] = av.w;

            // --- B tile: 16 rows x 128 cols = 512 float4s, 2 per thread ---
            #pragma unroll
            for (int t = 0; t < 2; t++) {
                int i    = tid * 2 + t;       // 0..511
                int brow = i >> 5;
                int bq   = i & 31;
                float4 bv = *reinterpret_cast<const float4*>(
                    B + (size_t)(kk + brow) * D_DIM + bq * 4);
                *reinterpret_cast<float4*>(&Bs[brow][bq * 4]) = bv;
            }
            __syncthreads();

            #pragma unroll
            for (int k = 0; k < 16; k++) {
                float a[8];
                #pragma unroll
                for (int i = 0; i < 8; i++) a[i] = As[k][trow * 8 + i];
                float4 bv = *reinterpret_cast<const float4*>(&Bs[k][tcol * 4]);
                float b[4] = {bv.x, bv.y, bv.z, bv.w};
                #pragma unroll
                for (int i = 0; i < 8; i++)
                    #pragma unroll
                    for (int j = 0; j < 4; j++)
                        acc[i][j] = fmaf(a[i], b[j], acc[i][j]);
            }
            __syncthreads();
        }
    }

    // --- epilogue: bias + leaky_relu, vectorized store ---
    float4 bvec = *reinterpret_cast<const float4*>(bias_l + tcol * 4);
    float bb[4] = {bvec.x, bvec.y, bvec.z, bvec.w};
    #pragma unroll
    for (int i = 0; i < 8; i++) {
        int row = m0 + trow * 8 + i;
        if (row < n) {
            float4 ov;
            float v0 = acc[i][0] + bb[0];
            float v1 = acc[i][1] + bb[1];
            float v2 = acc[i][2] + bb[2];
            float v3 = acc[i][3] + bb[3];
            ov.x = v0 > 0.f ? v0 : 0.01f * v0;
            ov.y = v1 > 0.f ? v1 : 0.01f * v1;
            ov.z = v2 > 0.f ? v2 : 0.01f * v2;
            ov.w = v3 > 0.f ? v3 : 0.01f * v3;
            *reinterpret_cast<float4*>(y + (size_t)row * D_DIM + tcol * 4) = ov;
        }
    }
}

// ---------------------------------------------------------------------------
// Launch: embed, then 3x (zero h -> scatter -> fused gemm)
// ---------------------------------------------------------------------------
extern "C" void kernel_launch(void* const* d_in, const int* in_sizes, int n_in,
                              void* d_out, int out_size)
{
    const int*   node_type  = (const int*)  d_in[0];
    const int*   edge_index = (const int*)  d_in[1];
    const int*   edge_type  = (const int*)  d_in[2];
    const float* emb        = (const float*)d_in[3];
    const float* W          = (const float*)d_in[4];   // [L,R,D,D]
    const float* root       = (const float*)d_in[5];   // [L,D,D]
    const float* bias       = (const float*)d_in[6];   // [L,D]
    float*       out        = (float*)d_out;

    const int n = in_sizes[0];
    const int E = in_sizes[2];

    float *xA, *xB, *h;
    cudaGetSymbolAddress((void**)&xA, g_xA);
    cudaGetSymbolAddress((void**)&xB, g_xB);
    cudaGetSymbolAddress((void**)&h,  g_h);

    // embed
    {
        int total = n * 32;
        embed_kernel<<<(total + 255) / 256, 256>>>(node_type, emb, xA, n);
    }

    const size_t h_bytes = (size_t)n * R_REL * D_DIM * sizeof(float);
    const int scatter_blocks = (E * 32 + 255) / 256;
    const int gemm_blocks    = (n + 63) / 64;

    for (int l = 0; l < L_LAY; l++) {
        const float* xin  = (l == 0) ? xA : (l == 1) ? xB : xA;
        float*       xout = (l == 0) ? xB : (l == 1) ? xA : out;

        cudaMemsetAsync(h, 0, h_bytes);
        scatter_kernel<<<scatter_blocks, 256>>>(edge_index, edge_type, xin, h, E);
        layer_gemm_kernel<<<gemm_blocks, 256>>>(
            xin, h,
            root + (size_t)l * D_DIM * D_DIM,
            W    + (size_t)l * R_REL * D_DIM * D_DIM,
            bias + (size_t)l * D_DIM,
            xout, n);
    }
}

// round 3
// speedup vs baseline: 1.6889x; 1.6889x over previous
#include <cuda_runtime.h>
#include <cuda_bf16.h>
#include <cstdint>

#define N_NODES 50000
#define D_DIM   128
#define R_REL   4
#define L_LAY   3
#define KTOT    640          // 128 (root) + 4*128 (W)
#define KC      64           // K per chunk
#define NCHUNK  (KTOT / KC)  // 10

// ---------------------------------------------------------------------------
// Scratch (static device arrays — no runtime allocation allowed)
// ---------------------------------------------------------------------------
__device__ float g_xA[(size_t)N_NODES * D_DIM];
__device__ float g_xB[(size_t)N_NODES * D_DIM];
__device__ float g_h [(size_t)N_NODES * R_REL * D_DIM];
// Transposed + bf16-split stacked weights: Bt[l][n][k], k in [0,640)
__device__ __nv_bfloat16 g_Bhi[L_LAY][D_DIM][KTOT];
__device__ __nv_bfloat16 g_Blo[L_LAY][D_DIM][KTOT];

#define SWZ128(off) ((off) ^ (((off) >> 3) & 0x70))

__device__ __forceinline__ uint32_t smem_u32(const void* p) {
    uint32_t a;
    asm("{ .reg .u64 t; cvta.to.shared.u64 t, %1; cvt.u32.u64 %0, t; }"
        : "=r"(a) : "l"(p));
    return a;
}

__device__ __forceinline__ void ldmatrix_x4(uint32_t& r0, uint32_t& r1,
                                            uint32_t& r2, uint32_t& r3,
                                            uint32_t addr) {
    asm volatile("ldmatrix.sync.aligned.m8n8.x4.shared.b16 {%0,%1,%2,%3}, [%4];"
                 : "=r"(r0), "=r"(r1), "=r"(r2), "=r"(r3) : "r"(addr));
}

__device__ __forceinline__ void mma_bf16(float* c, const uint32_t* a,
                                         uint32_t b0, uint32_t b1) {
    asm volatile(
        "mma.sync.aligned.m16n8k16.row.col.f32.bf16.bf16.f32 "
        "{%0,%1,%2,%3}, {%4,%5,%6,%7}, {%8,%9}, {%0,%1,%2,%3};"
        : "+f"(c[0]), "+f"(c[1]), "+f"(c[2]), "+f"(c[3])
        : "r"(a[0]), "r"(a[1]), "r"(a[2]), "r"(a[3]), "r"(b0), "r"(b1));
}

// ---------------------------------------------------------------------------
// Kernel 1: x = emb[node_type]
// ---------------------------------------------------------------------------
__global__ void embed_kernel(const int* __restrict__ node_type,
                             const float* __restrict__ emb,
                             float* __restrict__ x, int n)
{
    int idx = blockIdx.x * blockDim.x + threadIdx.x;
    if (idx >= n * 32) return;
    int node = idx >> 5;
    int q    = idx & 31;
    float4 v = reinterpret_cast<const float4*>(emb + (size_t)node_type[node] * D_DIM)[q];
    reinterpret_cast<float4*>(x + (size_t)node * D_DIM)[q] = v;
}

// ---------------------------------------------------------------------------
// Kernel 2: per-relation scatter-add (vectorized global reduction)
// ---------------------------------------------------------------------------
__global__ void scatter_kernel(const int* __restrict__ edge_index,
                               const int* __restrict__ edge_type,
                               const float* __restrict__ x,
                               float* __restrict__ h, int E)
{
    int warp = (blockIdx.x * blockDim.x + threadIdx.x) >> 5;
    int lane = threadIdx.x & 31;
    if (warp >= E) return;
    int src = edge_index[warp];
    int dst = edge_index[E + warp];
    int r   = edge_type[warp];
    float4 v = reinterpret_cast<const float4*>(x + (size_t)src * D_DIM)[lane];
    float* p = h + (size_t)dst * (R_REL * D_DIM) + r * D_DIM + lane * 4;
    asm volatile("red.global.add.v4.f32 [%0], {%1,%2,%3,%4};"
                 :: "l"(p), "f"(v.x), "f"(v.y), "f"(v.z), "f"(v.w) : "memory");
}

// ---------------------------------------------------------------------------
// Kernel 3 (prep, once): split stacked weights into transposed bf16 hi/lo.
// Bt[l][n][k] = stacked[l][k][n]; stacked rows 0..127 = root, 128..639 = W.
// ---------------------------------------------------------------------------
__global__ void prep_kernel(const float* __restrict__ W,
                            const float* __restrict__ root)
{
    int idx = blockIdx.x * blockDim.x + threadIdx.x;
    const int TOT = L_LAY * D_DIM * KTOT;
    if (idx >= TOT) return;
    int l  = idx / (D_DIM * KTOT);
    int r0 = idx % (D_DIM * KTOT);
    int nn = r0 / KTOT;
    int k  = r0 % KTOT;
    float v;
    if (k < D_DIM) {
        v = root[((size_t)l * D_DIM + k) * D_DIM + nn];
    } else {
        int kk = k - D_DIM;
        int r  = kk >> 7;
        int k2 = kk & 127;
        v = W[((((size_t)l * R_REL) + r) * D_DIM + k2) * D_DIM + nn];
    }
    __nv_bfloat16 hi = __float2bfloat16(v);
    __nv_bfloat16 lo = __float2bfloat16(v - __bfloat162float(hi));
    g_Bhi[l][nn][k] = hi;
    g_Blo[l][nn][k] = lo;
}

// ---------------------------------------------------------------------------
// Kernel 4: mma.sync bf16-split GEMM + bias + leaky_relu.
//   y[m, 0:128] = lrelu( [x | h][m, 0:640] @ Bt^T + bias )
// CTA: 128x128 tile, 256 threads = 8 warps in 2x4; warp tile 64x32.
// SMEM (dynamic, 64KB): Ahi, Alo, Bhi, Blo each [128][64] bf16 SW128-swizzled.
// ---------------------------------------------------------------------------
#define SM_AHI  0
#define SM_ALO  16384
#define SM_BHI  32768
#define SM_BLO  49152
#define SM_TOTAL 65536

__global__ __launch_bounds__(256, 2)
void gemm_mma_kernel(const float* __restrict__ x,
                     const float* __restrict__ h,
                     const __nv_bfloat16* __restrict__ Bhi,   // [128][640]
                     const __nv_bfloat16* __restrict__ Blo,
                     const float* __restrict__ bias_l,
                     float* __restrict__ y, int n)
{
    extern __shared__ __align__(1024) char smem[];
    const uint32_t sb = smem_u32(smem);
    const int tid    = threadIdx.x;
    const int lane   = tid & 31;
    const int wid    = tid >> 5;
    const int warp_m = wid >> 2;        // 0..1 -> 64 rows each
    const int warp_n = wid & 3;         // 0..3 -> 32 cols each
    const int m0     = blockIdx.x * 128;

    float acc[4][4][4];                 // [mtile][ntile][frag]
    #pragma unroll
    for (int i = 0; i < 4; i++)
        #pragma unroll
        for (int j = 0; j < 4; j++)
            #pragma unroll
            for (int q = 0; q < 4; q++) acc[i][j][q] = 0.f;

    for (int c = 0; c < NCHUNK; c++) {
        // ---- A chunk: 128 rows x 64 fp32 -> bf16 hi/lo, SW128 ----
        const float* Ap;
        int lda;
        if (c < 2) { Ap = x + c * KC; lda = D_DIM; }
        else       { Ap = h + (c - 2) * KC; lda = R_REL * D_DIM; }

        #pragma unroll
        for (int it = 0; it < 8; it++) {
            int f   = it * 256 + tid;        // float4 index, 0..2047
            int row = f >> 4;
            int q   = f & 15;
            float4 v = make_float4(0.f, 0.f, 0.f, 0.f);
            if (m0 + row < n)
                v = *reinterpret_cast<const float4*>(Ap + (size_t)(m0 + row) * lda + q * 4);
            __nv_bfloat16 h0 = __float2bfloat16(v.x);
            __nv_bfloat16 h1 = __float2bfloat16(v.y);
            __nv_bfloat16 h2 = __float2bfloat16(v.z);
            __nv_bfloat16 h3 = __float2bfloat16(v.w);
            __nv_bfloat16 l0 = __float2bfloat16(v.x - __bfloat162float(h0));
            __nv_bfloat16 l1 = __float2bfloat16(v.y - __bfloat162float(h1));
            __nv_bfloat16 l2 = __float2bfloat16(v.z - __bfloat162float(h2));
            __nv_bfloat16 l3 = __float2bfloat16(v.w - __bfloat162float(h3));
            uint32_t hp0 = ((uint32_t)__bfloat16_as_ushort(h1) << 16) | __bfloat16_as_ushort(h0);
            uint32_t hp1 = ((uint32_t)__bfloat16_as_ushort(h3) << 16) | __bfloat16_as_ushort(h2);
            uint32_t lp0 = ((uint32_t)__bfloat16_as_ushort(l1) << 16) | __bfloat16_as_ushort(l0);
            uint32_t lp1 = ((uint32_t)__bfloat16_as_ushort(l3) << 16) | __bfloat16_as_ushort(l2);
            uint32_t off = SWZ128((uint32_t)(row * 128 + q * 8));
            *reinterpret_cast<uint2*>(smem + SM_AHI + off) = make_uint2(hp0, hp1);
            *reinterpret_cast<uint2*>(smem + SM_ALO + off) = make_uint2(lp0, lp1);
        }

        // ---- B chunk: 128 (n) x 64 (k) bf16 hi/lo, SW128 ----
        const __nv_bfloat16* Bh = Bhi + c * KC;
        const __nv_bfloat16* Bl = Blo + c * KC;
        #pragma unroll
        for (int it = 0; it < 8; it++) {
            int f   = it * 256 + tid;        // uint2 index, 0..2047
            int row = f >> 4;
            int q   = f & 15;
            uint2 vh = *reinterpret_cast<const uint2*>(Bh + (size_t)row * KTOT + q * 4);
            uint2 vl = *reinterpret_cast<const uint2*>(Bl + (size_t)row * KTOT + q * 4);
            uint32_t off = SWZ128((uint32_t)(row * 128 + q * 8));
            *reinterpret_cast<uint2*>(smem + SM_BHI + off) = vh;
            *reinterpret_cast<uint2*>(smem + SM_BLO + off) = vl;
        }

        __syncthreads();

        // ---- compute: 4 k16-steps ----
        #pragma unroll
        for (int ks = 0; ks < 4; ks++) {
            const int k0 = ks * 16;

            // B fragments: 2 ldmatrix.x4 per hi/lo, covering 4 n-tiles of 8
            uint32_t bh[2][4], bl[2][4];
            #pragma unroll
            for (int p = 0; p < 2; p++) {
                int nb   = warp_n * 32 + p * 16;
                int row  = nb + (lane & 7) + ((lane >> 4) << 3);
                int byte = row * 128 + k0 * 2 + ((lane & 8) ? 16 : 0);
                uint32_t off = SWZ128((uint32_t)byte);
                ldmatrix_x4(bh[p][0], bh[p][1], bh[p][2], bh[p][3], sb + SM_BHI + off);
                ldmatrix_x4(bl[p][0], bl[p][1], bl[p][2], bl[p][3], sb + SM_BLO + off);
            }

            #pragma unroll
            for (int m = 0; m < 4; m++) {
                int mb   = warp_m * 64 + m * 16;
                int row  = mb + (lane & 15);
                int byte = row * 128 + k0 * 2 + ((lane >> 4) << 4);
                uint32_t off = SWZ128((uint32_t)byte);
                uint32_t ah[4], al[4];
                ldmatrix_x4(ah[0], ah[1], ah[2], ah[3], sb + SM_AHI + off);
                ldmatrix_x4(al[0], al[1], al[2], al[3], sb + SM_ALO + off);

                #pragma unroll
                for (int p = 0; p < 2; p++) {
                    #pragma unroll
                    for (int t = 0; t < 2; t++) {
                        int nt = p * 2 + t;
                        mma_bf16(acc[m][nt], ah, bh[p][t * 2], bh[p][t * 2 + 1]); // hi*hi
                        mma_bf16(acc[m][nt], ah, bl[p][t * 2], bl[p][t * 2 + 1]); // hi*lo
                        mma_bf16(acc[m][nt], al, bh[p][t * 2], bh[p][t * 2 + 1]); // lo*hi
                    }
                }
            }
        }
        __syncthreads();
    }

    // ---- epilogue: bias + leaky_relu, float2 stores ----
    #pragma unroll
    for (int nt = 0; nt < 4; nt++) {
        int col = warp_n * 32 + nt * 8 + (lane & 3) * 2;
        float2 b = *reinterpret_cast<const float2*>(bias_l + col);
        #pragma unroll
        for (int m = 0; m < 4; m++) {
            int row0 = m0 + warp_m * 64 + m * 16 + (lane >> 2);
            #pragma unroll
            for (int half = 0; half < 2; half++) {
                int row = row0 + half * 8;
                if (row < n) {
                    float v0 = acc[m][nt][half * 2 + 0] + b.x;
                    float v1 = acc[m][nt][half * 2 + 1] + b.y;
                    float2 ov;
                    ov.x = v0 > 0.f ? v0 : 0.01f * v0;
                    ov.y = v1 > 0.f ? v1 : 0.01f * v1;
                    *reinterpret_cast<float2*>(y + (size_t)row * D_DIM + col) = ov;
                }
            }
        }
    }
}

// ---------------------------------------------------------------------------
// Launch
// ---------------------------------------------------------------------------
extern "C" void kernel_launch(void* const* d_in, const int* in_sizes, int n_in,
                              void* d_out, int out_size)
{
    const int*   node_type  = (const int*)  d_in[0];
    const int*   edge_index = (const int*)  d_in[1];
    const int*   edge_type  = (const int*)  d_in[2];
    const float* emb        = (const float*)d_in[3];
    const float* W          = (const float*)d_in[4];   // [L,R,D,D]
    const float* root       = (const float*)d_in[5];   // [L,D,D]
    const float* bias       = (const float*)d_in[6];   // [L,D]
    float*       out        = (float*)d_out;

    const int n = in_sizes[0];
    const int E = in_sizes[2];

    float *xA, *xB, *h;
    __nv_bfloat16 *bhi, *blo;
    cudaGetSymbolAddress((void**)&xA,  g_xA);
    cudaGetSymbolAddress((void**)&xB,  g_xB);
    cudaGetSymbolAddress((void**)&h,   g_h);
    cudaGetSymbolAddress((void**)&bhi, g_Bhi);
    cudaGetSymbolAddress((void**)&blo, g_Blo);

    cudaFuncSetAttribute(gemm_mma_kernel,
                         cudaFuncAttributeMaxDynamicSharedMemorySize, SM_TOTAL);

    // embed + weight prep (independent)
    embed_kernel<<<(n * 32 + 255) / 256, 256>>>(node_type, emb, xA, n);
    {
        const int TOT = L_LAY * D_DIM * KTOT;
        prep_kernel<<<(TOT + 255) / 256, 256>>>(W, root);
    }

    const size_t h_bytes = (size_t)n * R_REL * D_DIM * sizeof(float);
    const int scatter_blocks = (E * 32 + 255) / 256;
    const int gemm_blocks    = (n + 127) / 128;

    for (int l = 0; l < L_LAY; l++) {
        const float* xin  = (l == 0) ? xA : (l == 1) ? xB : xA;
        float*       xout = (l == 0) ? xB : (l == 1) ? xA : out;

        cudaMemsetAsync(h, 0, h_bytes);
        scatter_kernel<<<scatter_blocks, 256>>>(edge_index, edge_type, xin, h, E);
        gemm_mma_kernel<<<gemm_blocks, 256, SM_TOTAL>>>(
            xin, h,
            bhi + (size_t)l * D_DIM * KTOT,
            blo + (size_t)l * D_DIM * KTOT,
            bias + (size_t)l * D_DIM,
            xout, n);
    }
}

// round 4
// speedup vs baseline: 2.0666x; 1.2236x over previous
#include <cuda_runtime.h>
#include <cuda_bf16.h>
#include <cstdint>

#define N_NODES 50000
#define E_MAX   600000
#define D_DIM   128
#define R_REL   4
#define L_LAY   3
#define KTOT    640           // 128 (root) + 4*128 (W)
#define KC      32            // K per pipeline stage
#define NCHUNK  (KTOT / KC)   // 20

// ---------------------------------------------------------------------------
// Static device scratch (no runtime allocation allowed)
// ---------------------------------------------------------------------------
__device__ __nv_bfloat16 g_xhiA[(size_t)N_NODES * D_DIM];
__device__ __nv_bfloat16 g_xloA[(size_t)N_NODES * D_DIM];
__device__ __nv_bfloat16 g_xhiB[(size_t)N_NODES * D_DIM];
__device__ __nv_bfloat16 g_xloB[(size_t)N_NODES * D_DIM];
__device__ __nv_bfloat16 g_hhi[(size_t)N_NODES * R_REL * D_DIM];
__device__ __nv_bfloat16 g_hlo[(size_t)N_NODES * R_REL * D_DIM];
// Transposed + bf16-split stacked weights: Bt[l][n][k], k in [0,640)
__device__ __nv_bfloat16 g_Bhi[L_LAY][D_DIM][KTOT];
__device__ __nv_bfloat16 g_Blo[L_LAY][D_DIM][KTOT];
// Edge sort
__device__ uint32_t g_sorted[E_MAX];
__device__ int      g_rowstart[N_NODES + 1];
__device__ int      g_cursor[N_NODES];

// ---------------------------------------------------------------------------
// Helpers
// ---------------------------------------------------------------------------
#define SWZ64(off) ((off) ^ (((off) >> 3) & 0x30))

__device__ __forceinline__ uint32_t smem_u32(const void* p) {
    uint32_t a;
    asm("{ .reg .u64 t; cvta.to.shared.u64 t, %1; cvt.u32.u64 %0, t; }"
        : "=r"(a) : "l"(p));
    return a;
}
__device__ __forceinline__ void cp16(uint32_t d, const void* s) {
    asm volatile("cp.async.cg.shared.global [%0], [%1], 16;" :: "r"(d), "l"(s));
}
__device__ __forceinline__ void cp16z(uint32_t d, const void* s, int bytes) {
    asm volatile("cp.async.cg.shared.global [%0], [%1], 16, %2;"
                 :: "r"(d), "l"(s), "r"(bytes));
}
#define CP_COMMIT() asm volatile("cp.async.commit_group;" ::: "memory")
#define CP_WAIT(N)  asm volatile("cp.async.wait_group %0;" :: "n"(N) : "memory")

__device__ __forceinline__ void ldmatrix_x4(uint32_t& r0, uint32_t& r1,
                                            uint32_t& r2, uint32_t& r3,
                                            uint32_t addr) {
    asm volatile("ldmatrix.sync.aligned.m8n8.x4.shared.b16 {%0,%1,%2,%3}, [%4];"
                 : "=r"(r0), "=r"(r1), "=r"(r2), "=r"(r3) : "r"(addr));
}
__device__ __forceinline__ void mma_bf16(float* c, const uint32_t* a,
                                         uint32_t b0, uint32_t b1) {
    asm volatile(
        "mma.sync.aligned.m16n8k16.row.col.f32.bf16.bf16.f32 "
        "{%0,%1,%2,%3}, {%4,%5,%6,%7}, {%8,%9}, {%0,%1,%2,%3};"
        : "+f"(c[0]), "+f"(c[1]), "+f"(c[2]), "+f"(c[3])
        : "r"(a[0]), "r"(a[1]), "r"(a[2]), "r"(a[3]), "r"(b0), "r"(b1));
}

__device__ __forceinline__ float bf_lo(uint32_t u) {
    return __bfloat162float(__ushort_as_bfloat16((unsigned short)(u & 0xffff)));
}
__device__ __forceinline__ float bf_hi(uint32_t u) {
    return __bfloat162float(__ushort_as_bfloat16((unsigned short)(u >> 16)));
}
__device__ __forceinline__ uint32_t pack2bf(float a, float b) {
    return ((uint32_t)__bfloat16_as_ushort(__float2bfloat16(b)) << 16) |
           (uint32_t)__bfloat16_as_ushort(__float2bfloat16(a));
}
// split v -> (hi, v-hi)
__device__ __forceinline__ void split1(float v, float& hi, float& lo) {
    __nv_bfloat16 h = __float2bfloat16(v);
    hi = __bfloat162float(h);
    lo = v - hi;
}

// ---------------------------------------------------------------------------
// Kernel: embed -> bf16 hi/lo split
// ---------------------------------------------------------------------------
__global__ void embed_kernel(const int* __restrict__ node_type,
                             const float* __restrict__ emb,
                             __nv_bfloat16* __restrict__ xhi,
                             __nv_bfloat16* __restrict__ xlo, int n)
{
    int idx = blockIdx.x * blockDim.x + threadIdx.x;
    if (idx >= n * 32) return;
    int node = idx >> 5;
    int q    = idx & 31;
    float4 v = reinterpret_cast<const float4*>(emb + (size_t)node_type[node] * D_DIM)[q];
    float h0, l0, h1, l1, h2, l2, h3, l3;
    split1(v.x, h0, l0); split1(v.y, h1, l1);
    split1(v.z, h2, l2); split1(v.w, h3, l3);
    uint2 ph = make_uint2(pack2bf(h0, h1), pack2bf(h2, h3));
    uint2 pl = make_uint2(pack2bf(l0, l1), pack2bf(l2, l3));
    *reinterpret_cast<uint2*>(xhi + (size_t)node * D_DIM + q * 4) = ph;
    *reinterpret_cast<uint2*>(xlo + (size_t)node * D_DIM + q * 4) = pl;
}

// ---------------------------------------------------------------------------
// Kernel: weight prep (transpose + split), once per launch
// ---------------------------------------------------------------------------
__global__ void prep_kernel(const float* __restrict__ W,
                            const float* __restrict__ root)
{
    int idx = blockIdx.x * blockDim.x + threadIdx.x;
    const int TOT = L_LAY * D_DIM * KTOT;
    if (idx >= TOT) return;
    int l  = idx / (D_DIM * KTOT);
    int r0 = idx % (D_DIM * KTOT);
    int nn = r0 / KTOT;
    int k  = r0 % KTOT;
    float v;
    if (k < D_DIM) {
        v = root[((size_t)l * D_DIM + k) * D_DIM + nn];
    } else {
        int kk = k - D_DIM;
        int r  = kk >> 7;
        int k2 = kk & 127;
        v = W[((((size_t)l * R_REL) + r) * D_DIM + k2) * D_DIM + nn];
    }
    float hi, lo;
    split1(v, hi, lo);
    g_Bhi[l][nn][k] = __float2bfloat16(hi);
    g_Blo[l][nn][k] = __float2bfloat16(lo);
}

// ---------------------------------------------------------------------------
// Sort kernels: counting sort of edges by dst
// ---------------------------------------------------------------------------
__global__ void hist_kernel(const int* __restrict__ edge_index, int E)
{
    int idx = blockIdx.x * blockDim.x + threadIdx.x;
    if (idx >= E) return;
    atomicAdd(&g_cursor[edge_index[E + idx]], 1);
}

__global__ void scan_kernel(int n)
{
    __shared__ int sh[1024];
    const int T   = 1024;
    const int tid = threadIdx.x;
    const int per = (n + T - 1) / T;
    const int start = tid * per;
    const int end   = min(start + per, n);
    int s = 0;
    for (int i = start; i < end; i++) s += g_cursor[i];
    sh[tid] = s;
    __syncthreads();
    #pragma unroll
    for (int d = 1; d < T; d <<= 1) {
        int v = (tid >= d) ? sh[tid - d] : 0;
        __syncthreads();
        sh[tid] += v;
        __syncthreads();
    }
    int off = (tid == 0) ? 0 : sh[tid - 1];
    for (int i = start; i < end; i++) {
        int c = g_cursor[i];
        g_rowstart[i] = off;
        g_cursor[i]   = off;
        off += c;
    }
    if (start < n && end == n) g_rowstart[n] = off;
}

__global__ void reorder_kernel(const int* __restrict__ edge_index,
                               const int* __restrict__ edge_type, int E)
{
    int idx = blockIdx.x * blockDim.x + threadIdx.x;
    if (idx >= E) return;
    int dst = edge_index[E + idx];
    int pos = atomicAdd(&g_cursor[dst], 1);
    g_sorted[pos] = ((uint32_t)edge_index[idx] << 2) | (uint32_t)edge_type[idx];
}

// ---------------------------------------------------------------------------
// Kernel: CSR aggregation. One warp per dst node.
//   h[dst, r*128+col] = sum over edges (src,r) of x[src, col]
// Reads bf16 hi/lo x; writes bf16 hi/lo h (all entries, zeros included).
// ---------------------------------------------------------------------------
__global__ __launch_bounds__(256)
void agg_kernel(const __nv_bfloat16* __restrict__ xhi,
                const __nv_bfloat16* __restrict__ xlo,
                __nv_bfloat16* __restrict__ hhi,
                __nv_bfloat16* __restrict__ hlo, int n)
{
    int w = (blockIdx.x * blockDim.x + threadIdx.x) >> 5;
    int lane = threadIdx.x & 31;
    if (w >= n) return;
    int e0 = g_rowstart[w];
    int e1 = g_rowstart[w + 1];

    float acc[R_REL][4];
    #pragma unroll
    for (int r = 0; r < R_REL; r++)
        #pragma unroll
        for (int j = 0; j < 4; j++) acc[r][j] = 0.f;

    for (int e = e0; e < e1; e++) {
        uint32_t sr = __ldg(&g_sorted[e]);
        int src = sr >> 2;
        int r   = sr & 3;
        uint2 vh = *reinterpret_cast<const uint2*>(xhi + (size_t)src * D_DIM + lane * 4);
        uint2 vl = *reinterpret_cast<const uint2*>(xlo + (size_t)src * D_DIM + lane * 4);
        acc[r][0] += bf_lo(vh.x) + bf_lo(vl.x);
        acc[r][1] += bf_hi(vh.x) + bf_hi(vl.x);
        acc[r][2] += bf_lo(vh.y) + bf_lo(vl.y);
        acc[r][3] += bf_hi(vh.y) + bf_hi(vl.y);
    }

    #pragma unroll
    for (int r = 0; r < R_REL; r++) {
        float h0, l0, h1, l1, h2, l2, h3, l3;
        split1(acc[r][0], h0, l0); split1(acc[r][1], h1, l1);
        split1(acc[r][2], h2, l2); split1(acc[r][3], h3, l3);
        size_t o = (size_t)w * (R_REL * D_DIM) + r * D_DIM + lane * 4;
        *reinterpret_cast<uint2*>(hhi + o) = make_uint2(pack2bf(h0, h1), pack2bf(h2, h3));
        *reinterpret_cast<uint2*>(hlo + o) = make_uint2(pack2bf(l0, l1), pack2bf(l2, l3));
    }
}

// ---------------------------------------------------------------------------
// GEMM: y[m,0:128] = lrelu( [x|h][m,0:640] @ Bt^T + bias )
// All operands bf16 hi/lo in global. CTA 128x128, 256 thr (8 warps 2x4).
// cp.async double-buffered KC=32 stages; SW64 swizzle; 3-term split MMA.
// Output: fp32 (final layer) OR bf16 hi/lo split (intermediate layers).
// ---------------------------------------------------------------------------
#define ST_AHI 0
#define ST_ALO 8192
#define ST_BHI 16384
#define ST_BLO 24576
#define ST_SIZE 32768
#define SM_TOTAL (2 * ST_SIZE)

__global__ __launch_bounds__(256, 2)
void gemm_mma_kernel(const __nv_bfloat16* __restrict__ xhi,
                     const __nv_bfloat16* __restrict__ xlo,
                     const __nv_bfloat16* __restrict__ hhi,
                     const __nv_bfloat16* __restrict__ hlo,
                     const __nv_bfloat16* __restrict__ Bhi,   // [128][640]
                     const __nv_bfloat16* __restrict__ Blo,
                     const float* __restrict__ bias_l,
                     __nv_bfloat16* __restrict__ yhi,         // null on final
                     __nv_bfloat16* __restrict__ ylo,
                     float* __restrict__ yf32,                // null unless final
                     int n)
{
    extern __shared__ __align__(1024) char smem[];
    const uint32_t sb = smem_u32(smem);
    const int tid    = threadIdx.x;
    const int lane   = tid & 31;
    const int wid    = tid >> 5;
    const int warp_m = wid >> 2;        // 0..1 -> 64 rows
    const int warp_n = wid & 3;         // 0..3 -> 32 cols
    const int m0     = blockIdx.x * 128;

    float acc[4][4][4];
    #pragma unroll
    for (int i = 0; i < 4; i++)
        #pragma unroll
        for (int j = 0; j < 4; j++)
            #pragma unroll
            for (int q = 0; q < 4; q++) acc[i][j][q] = 0.f;

    // ---- stage loader ----
    auto load_stage = [&](int stage, int c) {
        const __nv_bfloat16 *Ah, *Al;
        int lda;
        if (c < 4) { Ah = xhi + c * KC; Al = xlo + c * KC; lda = D_DIM; }
        else       { Ah = hhi + (c - 4) * KC; Al = hlo + (c - 4) * KC; lda = R_REL * D_DIM; }
        const uint32_t base = sb + stage * ST_SIZE;
        #pragma unroll
        for (int it = 0; it < 2; it++) {
            int f   = it * 256 + tid;     // 0..511
            int row = f >> 2;
            int q   = f & 3;
            uint32_t off = SWZ64((uint32_t)(row * 64 + q * 16));
            int bytes = (m0 + row < n) ? 16 : 0;
            cp16z(base + ST_AHI + off, Ah + (size_t)(m0 + row) * lda + q * 8, bytes);
            cp16z(base + ST_ALO + off, Al + (size_t)(m0 + row) * lda + q * 8, bytes);
        }
        #pragma unroll
        for (int it = 0; it < 2; it++) {
            int f   = it * 256 + tid;
            int row = f >> 2;             // n index 0..127
            int q   = f & 3;
            uint32_t off = SWZ64((uint32_t)(row * 64 + q * 16));
            cp16(base + ST_BHI + off, Bhi + (size_t)row * KTOT + c * KC + q * 8);
            cp16(base + ST_BLO + off, Blo + (size_t)row * KTOT + c * KC + q * 8);
        }
    };

    load_stage(0, 0);
    CP_COMMIT();

    for (int c = 0; c < NCHUNK; c++) {
        if (c + 1 < NCHUNK) {
            load_stage((c + 1) & 1, c + 1);
            CP_COMMIT();
            CP_WAIT(1);
        } else {
            CP_WAIT(0);
        }
        __syncthreads();

        const uint32_t base = sb + (c & 1) * ST_SIZE;
        #pragma unroll
        for (int ks = 0; ks < 2; ks++) {
            const int k0 = ks * 16;
            uint32_t bh[2][4], bl[2][4];
            #pragma unroll
            for (int p = 0; p < 2; p++) {
                int nb   = warp_n * 32 + p * 16;
                int row  = nb + (lane & 7) + ((lane >> 4) << 3);
                uint32_t off = SWZ64((uint32_t)(row * 64 + k0 * 2 + ((lane & 8) ? 16 : 0)));
                ldmatrix_x4(bh[p][0], bh[p][1], bh[p][2], bh[p][3], base + ST_BHI + off);
                ldmatrix_x4(bl[p][0], bl[p][1], bl[p][2], bl[p][3], base + ST_BLO + off);
            }
            #pragma unroll
            for (int m = 0; m < 4; m++) {
                int row  = warp_m * 64 + m * 16 + (lane & 15);
                uint32_t off = SWZ64((uint32_t)(row * 64 + k0 * 2 + ((lane >> 4) << 4)));
                uint32_t ah[4], al[4];
                ldmatrix_x4(ah[0], ah[1], ah[2], ah[3], base + ST_AHI + off);
                ldmatrix_x4(al[0], al[1], al[2], al[3], base + ST_ALO + off);
                #pragma unroll
                for (int p = 0; p < 2; p++) {
                    #pragma unroll
                    for (int t = 0; t < 2; t++) {
                        int nt = p * 2 + t;
                        mma_bf16(acc[m][nt], ah, bh[p][t * 2], bh[p][t * 2 + 1]);
                        mma_bf16(acc[m][nt], ah, bl[p][t * 2], bl[p][t * 2 + 1]);
                        mma_bf16(acc[m][nt], al, bh[p][t * 2], bh[p][t * 2 + 1]);
                    }
                }
            }
        }
        __syncthreads();
    }

    // ---- epilogue ----
    #pragma unroll
    for (int nt = 0; nt < 4; nt++) {
        int col = warp_n * 32 + nt * 8 + (lane & 3) * 2;
        float2 b = *reinterpret_cast<const float2*>(bias_l + col);
        #pragma unroll
        for (int m = 0; m < 4; m++) {
            int row0 = m0 + warp_m * 64 + m * 16 + (lane >> 2);
            #pragma unroll
            for (int half = 0; half < 2; half++) {
                int row = row0 + half * 8;
                if (row < n) {
                    float v0 = acc[m][nt][half * 2 + 0] + b.x;
                    float v1 = acc[m][nt][half * 2 + 1] + b.y;
                    v0 = v0 > 0.f ? v0 : 0.01f * v0;
                    v1 = v1 > 0.f ? v1 : 0.01f * v1;
                    if (yf32) {
                        float2 ov = make_float2(v0, v1);
                        *reinterpret_cast<float2*>(yf32 + (size_t)row * D_DIM + col) = ov;
                    } else {
                        float h0, l0, h1, l1;
                        split1(v0, h0, l0);
                        split1(v1, h1, l1);
                        *reinterpret_cast<uint32_t*>(yhi + (size_t)row * D_DIM + col) =
                            pack2bf(h0, h1);
                        *reinterpret_cast<uint32_t*>(ylo + (size_t)row * D_DIM + col) =
                            pack2bf(l0, l1);
                    }
                }
            }
        }
    }
}

// ---------------------------------------------------------------------------
// Launch
// ---------------------------------------------------------------------------
extern "C" void kernel_launch(void* const* d_in, const int* in_sizes, int n_in,
                              void* d_out, int out_size)
{
    const int*   node_type  = (const int*)  d_in[0];
    const int*   edge_index = (const int*)  d_in[1];
    const int*   edge_type  = (const int*)  d_in[2];
    const float* emb        = (const float*)d_in[3];
    const float* W          = (const float*)d_in[4];   // [L,R,D,D]
    const float* root       = (const float*)d_in[5];   // [L,D,D]
    const float* bias       = (const float*)d_in[6];   // [L,D]
    float*       out        = (float*)d_out;

    const int n = in_sizes[0];
    const int E = in_sizes[2];

    __nv_bfloat16 *xhiA, *xloA, *xhiB, *xloB, *hhi, *hlo, *bhi, *blo;
    int* cursor;
    cudaGetSymbolAddress((void**)&xhiA, g_xhiA);
    cudaGetSymbolAddress((void**)&xloA, g_xloA);
    cudaGetSymbolAddress((void**)&xhiB, g_xhiB);
    cudaGetSymbolAddress((void**)&xloB, g_xloB);
    cudaGetSymbolAddress((void**)&hhi,  g_hhi);
    cudaGetSymbolAddress((void**)&hlo,  g_hlo);
    cudaGetSymbolAddress((void**)&bhi,  g_Bhi);
    cudaGetSymbolAddress((void**)&blo,  g_Blo);
    cudaGetSymbolAddress((void**)&cursor, g_cursor);

    cudaFuncSetAttribute(gemm_mma_kernel,
                         cudaFuncAttributeMaxDynamicSharedMemorySize, SM_TOTAL);

    // --- one-time per launch: embed split, weight prep, edge sort ---
    cudaMemsetAsync(cursor, 0, (size_t)n * sizeof(int));
    embed_kernel<<<(n * 32 + 255) / 256, 256>>>(node_type, emb, xhiA, xloA, n);
    {
        const int TOT = L_LAY * D_DIM * KTOT;
        prep_kernel<<<(TOT + 255) / 256, 256>>>(W, root);
    }
    hist_kernel<<<(E + 255) / 256, 256>>>(edge_index, E);
    scan_kernel<<<1, 1024>>>(n);
    reorder_kernel<<<(E + 255) / 256, 256>>>(edge_index, edge_type, E);

    const int agg_blocks  = (n * 32 + 255) / 256;
    const int gemm_blocks = (n + 127) / 128;

    for (int l = 0; l < L_LAY; l++) {
        const __nv_bfloat16* xih = (l == 1) ? xhiB : xhiA;
        const __nv_bfloat16* xil = (l == 1) ? xloB : xloA;
        __nv_bfloat16* xoh = (l == 0) ? xhiB : xhiA;
        __nv_bfloat16* xol = (l == 0) ? xloB : xloA;

        agg_kernel<<<agg_blocks, 256>>>(xih, xil, hhi, hlo, n);

        if (l < L_LAY - 1) {
            gemm_mma_kernel<<<gemm_blocks, 256, SM_TOTAL>>>(
                xih, xil, hhi, hlo,
                bhi + (size_t)l * D_DIM * KTOT,
                blo + (size_t)l * D_DIM * KTOT,
                bias + (size_t)l * D_DIM,
                xoh, xol, (float*)nullptr, n);
        } else {
            gemm_mma_kernel<<<gemm_blocks, 256, SM_TOTAL>>>(
                xih, xil, hhi, hlo,
                bhi + (size_t)l * D_DIM * KTOT,
                blo + (size_t)l * D_DIM * KTOT,
                bias + (size_t)l * D_DIM,
                (__nv_bfloat16*)nullptr, (__nv_bfloat16*)nullptr, out, n);
        }
    }
}

// round 6
// speedup vs baseline: 2.3773x; 1.1503x over previous
#include <cuda_runtime.h>
#include <cuda_bf16.h>
#include <cstdint>

#define N_NODES 50000
#define E_MAX   600000
#define D_DIM   128
#define R_REL   4
#define L_LAY   3
#define KTOT    640           // 128 (root) + 4*128 (W)
#define KC      32            // K per pipeline stage
#define NCHUNK  (KTOT / KC)   // 20

// ---------------------------------------------------------------------------
// Static device scratch (no runtime allocation allowed)
// ---------------------------------------------------------------------------
__device__ __nv_bfloat16 g_xhiA[(size_t)N_NODES * D_DIM];
__device__ __nv_bfloat16 g_xloA[(size_t)N_NODES * D_DIM];
__device__ __nv_bfloat16 g_xhiB[(size_t)N_NODES * D_DIM];
__device__ __nv_bfloat16 g_xloB[(size_t)N_NODES * D_DIM];
__device__ __nv_bfloat16 g_hhi[(size_t)N_NODES * R_REL * D_DIM];
__device__ __nv_bfloat16 g_hlo[(size_t)N_NODES * R_REL * D_DIM];
// Transposed + bf16-split stacked weights: Bt[l][n][k], k in [0,640)
__device__ __nv_bfloat16 g_Bhi[L_LAY][D_DIM][KTOT];
__device__ __nv_bfloat16 g_Blo[L_LAY][D_DIM][KTOT];
// Edge sort
__device__ uint32_t g_sorted[E_MAX];
__device__ int      g_rowstart[N_NODES + 1];
__device__ int      g_cursor[N_NODES];
__device__ int      g_bsum[64];

// ---------------------------------------------------------------------------
// Helpers
// ---------------------------------------------------------------------------
#define SWZ64(off) ((off) ^ (((off) >> 3) & 0x30))

__device__ __forceinline__ uint32_t smem_u32(const void* p) {
    uint32_t a;
    asm("{ .reg .u64 t; cvta.to.shared.u64 t, %1; cvt.u32.u64 %0, t; }"
        : "=r"(a) : "l"(p));
    return a;
}
__device__ __forceinline__ void cp16(uint32_t d, const void* s) {
    asm volatile("cp.async.cg.shared.global [%0], [%1], 16;" :: "r"(d), "l"(s));
}
__device__ __forceinline__ void cp16z(uint32_t d, const void* s, int bytes) {
    asm volatile("cp.async.cg.shared.global [%0], [%1], 16, %2;"
                 :: "r"(d), "l"(s), "r"(bytes));
}
#define CP_COMMIT() asm volatile("cp.async.commit_group;" ::: "memory")
#define CP_WAIT(N)  asm volatile("cp.async.wait_group %0;" :: "n"(N) : "memory")

__device__ __forceinline__ void ldmatrix_x4(uint32_t& r0, uint32_t& r1,
                                            uint32_t& r2, uint32_t& r3,
                                            uint32_t addr) {
    asm volatile("ldmatrix.sync.aligned.m8n8.x4.shared.b16 {%0,%1,%2,%3}, [%4];"
                 : "=r"(r0), "=r"(r1), "=r"(r2), "=r"(r3) : "r"(addr));
}
__device__ __forceinline__ void mma_bf16(float* c, const uint32_t* a,
                                         uint32_t b0, uint32_t b1) {
    asm volatile(
        "mma.sync.aligned.m16n8k16.row.col.f32.bf16.bf16.f32 "
        "{%0,%1,%2,%3}, {%4,%5,%6,%7}, {%8,%9}, {%0,%1,%2,%3};"
        : "+f"(c[0]), "+f"(c[1]), "+f"(c[2]), "+f"(c[3])
        : "r"(a[0]), "r"(a[1]), "r"(a[2]), "r"(a[3]), "r"(b0), "r"(b1));
}

__device__ __forceinline__ float bf_lo(uint32_t u) {
    return __bfloat162float(__ushort_as_bfloat16((unsigned short)(u & 0xffff)));
}
__device__ __forceinline__ float bf_hi(uint32_t u) {
    return __bfloat162float(__ushort_as_bfloat16((unsigned short)(u >> 16)));
}
__device__ __forceinline__ uint32_t pack2bf(float a, float b) {
    return ((uint32_t)__bfloat16_as_ushort(__float2bfloat16(b)) << 16) |
           (uint32_t)__bfloat16_as_ushort(__float2bfloat16(a));
}
// split v -> (hi, v-hi)
__device__ __forceinline__ void split1(float v, float& hi, float& lo) {
    __nv_bfloat16 h = __float2bfloat16(v);
    hi = __bfloat162float(h);
    lo = v - hi;
}

// ---------------------------------------------------------------------------
// Kernel: embed -> bf16 hi/lo split
// ---------------------------------------------------------------------------
__global__ void embed_kernel(const int* __restrict__ node_type,
                             const float* __restrict__ emb,
                             __nv_bfloat16* __restrict__ xhi,
                             __nv_bfloat16* __restrict__ xlo, int n)
{
    int idx = blockIdx.x * blockDim.x + threadIdx.x;
    if (idx >= n * 32) return;
    int node = idx >> 5;
    int q    = idx & 31;
    float4 v = reinterpret_cast<const float4*>(emb + (size_t)node_type[node] * D_DIM)[q];
    float h0, l0, h1, l1, h2, l2, h3, l3;
    split1(v.x, h0, l0); split1(v.y, h1, l1);
    split1(v.z, h2, l2); split1(v.w, h3, l3);
    uint2 ph = make_uint2(pack2bf(h0, h1), pack2bf(h2, h3));
    uint2 pl = make_uint2(pack2bf(l0, l1), pack2bf(l2, l3));
    *reinterpret_cast<uint2*>(xhi + (size_t)node * D_DIM + q * 4) = ph;
    *reinterpret_cast<uint2*>(xlo + (size_t)node * D_DIM + q * 4) = pl;
}

// ---------------------------------------------------------------------------
// Kernel: weight prep (transpose + split), once per launch
// ---------------------------------------------------------------------------
__global__ void prep_kernel(const float* __restrict__ W,
                            const float* __restrict__ root)
{
    int idx = blockIdx.x * blockDim.x + threadIdx.x;
    const int TOT = L_LAY * D_DIM * KTOT;
    if (idx >= TOT) return;
    int l  = idx / (D_DIM * KTOT);
    int r0 = idx % (D_DIM * KTOT);
    int nn = r0 / KTOT;
    int k  = r0 % KTOT;
    float v;
    if (k < D_DIM) {
        v = root[((size_t)l * D_DIM + k) * D_DIM + nn];
    } else {
        int kk = k - D_DIM;
        int r  = kk >> 7;
        int k2 = kk & 127;
        v = W[((((size_t)l * R_REL) + r) * D_DIM + k2) * D_DIM + nn];
    }
    float hi, lo;
    split1(v, hi, lo);
    g_Bhi[l][nn][k] = __float2bfloat16(hi);
    g_Blo[l][nn][k] = __float2bfloat16(lo);
}

// ---------------------------------------------------------------------------
// Sort kernels: counting sort of edges by dst (3-phase parallel scan)
// ---------------------------------------------------------------------------
__global__ void hist_kernel(const int* __restrict__ edge_index, int E)
{
    int idx = blockIdx.x * blockDim.x + threadIdx.x;
    if (idx >= E) return;
    atomicAdd(&g_cursor[edge_index[E + idx]], 1);
}

// Phase A: per-block (1024-wide) exclusive scan of counts; block totals to g_bsum.
__global__ __launch_bounds__(1024)
void scanA_kernel(int n)
{
    __shared__ int warp_sums[32];
    const int tid  = threadIdx.x;
    const int lane = tid & 31;
    const int wrp  = tid >> 5;
    const int i    = blockIdx.x * 1024 + tid;
    int v = (i < n) ? g_cursor[i] : 0;
    int x = v;
    #pragma unroll
    for (int d = 1; d < 32; d <<= 1) {
        int t = __shfl_up_sync(0xffffffffu, x, d);
        if (lane >= d) x += t;
    }
    if (lane == 31) warp_sums[wrp] = x;
    __syncthreads();
    if (wrp == 0) {
        int s = warp_sums[lane];
        #pragma unroll
        for (int d = 1; d < 32; d <<= 1) {
            int t = __shfl_up_sync(0xffffffffu, s, d);
            if (lane >= d) s += t;
        }
        warp_sums[lane] = s;
    }
    __syncthreads();
    int excl = x - v + (wrp ? warp_sums[wrp - 1] : 0);
    if (i < n) g_rowstart[i] = excl;
    if (tid == 1023) g_bsum[blockIdx.x] = excl + v;   // block total
}

// Phase B: exclusive scan of the <=64 block totals (2 warps + smem).
__global__ void scanB_kernel(int nb)
{
    __shared__ int ws[2];
    const int tid  = threadIdx.x;   // 64
    const int lane = tid & 31;
    const int wrp  = tid >> 5;
    int v = (tid < nb) ? g_bsum[tid] : 0;
    int x = v;
    #pragma unroll
    for (int d = 1; d < 32; d <<= 1) {
        int t = __shfl_up_sync(0xffffffffu, x, d);
        if (lane >= d) x += t;
    }
    if (lane == 31) ws[wrp] = x;
    __syncthreads();
    int excl = x - v + (wrp ? ws[0] : 0);
    if (tid < nb) g_bsum[tid] = excl;
}

// Phase C: add block offsets; produce rowstart + cursor; rowstart[n] = E.
__global__ __launch_bounds__(1024)
void scanC_kernel(int n, int E)
{
    const int i = blockIdx.x * 1024 + threadIdx.x;
    if (i < n) {
        int v = g_rowstart[i] + g_bsum[blockIdx.x];
        g_rowstart[i] = v;
        g_cursor[i]   = v;
    } else if (i == n) {
        g_rowstart[n] = E;
    }
}

__global__ void reorder_kernel(const int* __restrict__ edge_index,
                               const int* __restrict__ edge_type, int E)
{
    int idx = blockIdx.x * blockDim.x + threadIdx.x;
    if (idx >= E) return;
    int dst = edge_index[E + idx];
    int pos = atomicAdd(&g_cursor[dst], 1);
    g_sorted[pos] = ((uint32_t)edge_index[idx] << 2) | (uint32_t)edge_type[idx];
}

// ---------------------------------------------------------------------------
// Kernel: CSR aggregation. One warp per dst node.
// ---------------------------------------------------------------------------
__global__ __launch_bounds__(256)
void agg_kernel(const __nv_bfloat16* __restrict__ xhi,
                const __nv_bfloat16* __restrict__ xlo,
                __nv_bfloat16* __restrict__ hhi,
                __nv_bfloat16* __restrict__ hlo, int n)
{
    int w = (blockIdx.x * blockDim.x + threadIdx.x) >> 5;
    int lane = threadIdx.x & 31;
    if (w >= n) return;
    int e0 = g_rowstart[w];
    int e1 = g_rowstart[w + 1];

    float acc[R_REL][4];
    #pragma unroll
    for (int r = 0; r < R_REL; r++)
        #pragma unroll
        for (int j = 0; j < 4; j++) acc[r][j] = 0.f;

    for (int e = e0; e < e1; e++) {
        uint32_t sr = __ldg(&g_sorted[e]);
        int src = sr >> 2;
        int r   = sr & 3;
        uint2 vh = *reinterpret_cast<const uint2*>(xhi + (size_t)src * D_DIM + lane * 4);
        uint2 vl = *reinterpret_cast<const uint2*>(xlo + (size_t)src * D_DIM + lane * 4);
        acc[r][0] += bf_lo(vh.x) + bf_lo(vl.x);
        acc[r][1] += bf_hi(vh.x) + bf_hi(vl.x);
        acc[r][2] += bf_lo(vh.y) + bf_lo(vl.y);
        acc[r][3] += bf_hi(vh.y) + bf_hi(vl.y);
    }

    #pragma unroll
    for (int r = 0; r < R_REL; r++) {
        float h0, l0, h1, l1, h2, l2, h3, l3;
        split1(acc[r][0], h0, l0); split1(acc[r][1], h1, l1);
        split1(acc[r][2], h2, l2); split1(acc[r][3], h3, l3);
        size_t o = (size_t)w * (R_REL * D_DIM) + r * D_DIM + lane * 4;
        *reinterpret_cast<uint2*>(hhi + o) = make_uint2(pack2bf(h0, h1), pack2bf(h2, h3));
        *reinterpret_cast<uint2*>(hlo + o) = make_uint2(pack2bf(l0, l1), pack2bf(l2, l3));
    }
}

// ---------------------------------------------------------------------------
// GEMM: y[m,0:128] = lrelu( [x|h][m,0:640] @ Bt^T + bias )
// ---------------------------------------------------------------------------
#define ST_AHI 0
#define ST_ALO 8192
#define ST_BHI 16384
#define ST_BLO 24576
#define ST_SIZE 32768
#define SM_TOTAL (2 * ST_SIZE)

__global__ __launch_bounds__(256, 2)
void gemm_mma_kernel(const __nv_bfloat16* __restrict__ xhi,
                     const __nv_bfloat16* __restrict__ xlo,
                     const __nv_bfloat16* __restrict__ hhi,
                     const __nv_bfloat16* __restrict__ hlo,
                     const __nv_bfloat16* __restrict__ Bhi,   // [128][640]
                     const __nv_bfloat16* __restrict__ Blo,
                     const float* __restrict__ bias_l,
                     __nv_bfloat16* __restrict__ yhi,         // null on final
                     __nv_bfloat16* __restrict__ ylo,
                     float* __restrict__ yf32,                // null unless final
                     int n)
{
    extern __shared__ __align__(1024) char smem[];
    const uint32_t sb = smem_u32(smem);
    const int tid    = threadIdx.x;
    const int lane   = tid & 31;
    const int wid    = tid >> 5;
    const int warp_m = wid >> 2;        // 0..1 -> 64 rows
    const int warp_n = wid & 3;         // 0..3 -> 32 cols
    const int m0     = blockIdx.x * 128;

    float acc[4][4][4];
    #pragma unroll
    for (int i = 0; i < 4; i++)
        #pragma unroll
        for (int j = 0; j < 4; j++)
            #pragma unroll
            for (int q = 0; q < 4; q++) acc[i][j][q] = 0.f;

    auto load_stage = [&](int stage, int c) {
        const __nv_bfloat16 *Ah, *Al;
        int lda;
        if (c < 4) { Ah = xhi + c * KC; Al = xlo + c * KC; lda = D_DIM; }
        else       { Ah = hhi + (c - 4) * KC; Al = hlo + (c - 4) * KC; lda = R_REL * D_DIM; }
        const uint32_t base = sb + stage * ST_SIZE;
        #pragma unroll
        for (int it = 0; it < 2; it++) {
            int f   = it * 256 + tid;     // 0..511
            int row = f >> 2;
            int q   = f & 3;
            uint32_t off = SWZ64((uint32_t)(row * 64 + q * 16));
            int bytes = (m0 + row < n) ? 16 : 0;
            cp16z(base + ST_AHI + off, Ah + (size_t)(m0 + row) * lda + q * 8, bytes);
            cp16z(base + ST_ALO + off, Al + (size_t)(m0 + row) * lda + q * 8, bytes);
        }
        #pragma unroll
        for (int it = 0; it < 2; it++) {
            int f   = it * 256 + tid;
            int row = f >> 2;             // n index 0..127
            int q   = f & 3;
            uint32_t off = SWZ64((uint32_t)(row * 64 + q * 16));
            cp16(base + ST_BHI + off, Bhi + (size_t)row * KTOT + c * KC + q * 8);
            cp16(base + ST_BLO + off, Blo + (size_t)row * KTOT + c * KC + q * 8);
        }
    };

    load_stage(0, 0);
    CP_COMMIT();

    for (int c = 0; c < NCHUNK; c++) {
        if (c + 1 < NCHUNK) {
            load_stage((c + 1) & 1, c + 1);
            CP_COMMIT();
            CP_WAIT(1);
        } else {
            CP_WAIT(0);
        }
        __syncthreads();

        const uint32_t base = sb + (c & 1) * ST_SIZE;
        #pragma unroll
        for (int ks = 0; ks < 2; ks++) {
            const int k0 = ks * 16;
            uint32_t bh[2][4], bl[2][4];
            #pragma unroll
            for (int p = 0; p < 2; p++) {
                int nb   = warp_n * 32 + p * 16;
                int row  = nb + (lane & 7) + ((lane >> 4) << 3);
                uint32_t off = SWZ64((uint32_t)(row * 64 + k0 * 2 + ((lane & 8) ? 16 : 0)));
                ldmatrix_x4(bh[p][0], bh[p][1], bh[p][2], bh[p][3], base + ST_BHI + off);
                ldmatrix_x4(bl[p][0], bl[p][1], bl[p][2], bl[p][3], base + ST_BLO + off);
            }
            #pragma unroll
            for (int m = 0; m < 4; m++) {
                int row  = warp_m * 64 + m * 16 + (lane & 15);
                uint32_t off = SWZ64((uint32_t)(row * 64 + k0 * 2 + ((lane >> 4) << 4)));
                uint32_t ah[4], al[4];
                ldmatrix_x4(ah[0], ah[1], ah[2], ah[3], base + ST_AHI + off);
                ldmatrix_x4(al[0], al[1], al[2], al[3], base + ST_ALO + off);
                #pragma unroll
                for (int p = 0; p < 2; p++) {
                    #pragma unroll
                    for (int t = 0; t < 2; t++) {
                        int nt = p * 2 + t;
                        mma_bf16(acc[m][nt], ah, bh[p][t * 2], bh[p][t * 2 + 1]);
                        mma_bf16(acc[m][nt], ah, bl[p][t * 2], bl[p][t * 2 + 1]);
                        mma_bf16(acc[m][nt], al, bh[p][t * 2], bh[p][t * 2 + 1]);
                    }
                }
            }
        }
        __syncthreads();
    }

    // ---- epilogue ----
    #pragma unroll
    for (int nt = 0; nt < 4; nt++) {
        int col = warp_n * 32 + nt * 8 + (lane & 3) * 2;
        float2 b = *reinterpret_cast<const float2*>(bias_l + col);
        #pragma unroll
        for (int m = 0; m < 4; m++) {
            int row0 = m0 + warp_m * 64 + m * 16 + (lane >> 2);
            #pragma unroll
            for (int half = 0; half < 2; half++) {
                int row = row0 + half * 8;
                if (row < n) {
                    float v0 = acc[m][nt][half * 2 + 0] + b.x;
                    float v1 = acc[m][nt][half * 2 + 1] + b.y;
                    v0 = v0 > 0.f ? v0 : 0.01f * v0;
                    v1 = v1 > 0.f ? v1 : 0.01f * v1;
                    if (yf32) {
                        float2 ov = make_float2(v0, v1);
                        *reinterpret_cast<float2*>(yf32 + (size_t)row * D_DIM + col) = ov;
                    } else {
                        float h0, l0, h1, l1;
                        split1(v0, h0, l0);
                        split1(v1, h1, l1);
                        *reinterpret_cast<uint32_t*>(yhi + (size_t)row * D_DIM + col) =
                            pack2bf(h0, h1);
                        *reinterpret_cast<uint32_t*>(ylo + (size_t)row * D_DIM + col) =
                            pack2bf(l0, l1);
                    }
                }
            }
        }
    }
}

// ---------------------------------------------------------------------------
// Launch
// ---------------------------------------------------------------------------
extern "C" void kernel_launch(void* const* d_in, const int* in_sizes, int n_in,
                              void* d_out, int out_size)
{
    const int*   node_type  = (const int*)  d_in[0];
    const int*   edge_index = (const int*)  d_in[1];
    const int*   edge_type  = (const int*)  d_in[2];
    const float* emb        = (const float*)d_in[3];
    const float* W          = (const float*)d_in[4];   // [L,R,D,D]
    const float* root       = (const float*)d_in[5];   // [L,D,D]
    const float* bias       = (const float*)d_in[6];   // [L,D]
    float*       out        = (float*)d_out;

    const int n = in_sizes[0];
    const int E = in_sizes[2];

    __nv_bfloat16 *xhiA, *xloA, *xhiB, *xloB, *hhi, *hlo, *bhi, *blo;
    int* cursor;
    cudaGetSymbolAddress((void**)&xhiA, g_xhiA);
    cudaGetSymbolAddress((void**)&xloA, g_xloA);
    cudaGetSymbolAddress((void**)&xhiB, g_xhiB);
    cudaGetSymbolAddress((void**)&xloB, g_xloB);
    cudaGetSymbolAddress((void**)&hhi,  g_hhi);
    cudaGetSymbolAddress((void**)&hlo,  g_hlo);
    cudaGetSymbolAddress((void**)&bhi,  g_Bhi);
    cudaGetSymbolAddress((void**)&blo,  g_Blo);
    cudaGetSymbolAddress((void**)&cursor, g_cursor);

    cudaFuncSetAttribute(gemm_mma_kernel,
                         cudaFuncAttributeMaxDynamicSharedMemorySize, SM_TOTAL);

    // --- one-time per launch: embed split, weight prep, edge sort ---
    cudaMemsetAsync(cursor, 0, (size_t)n * sizeof(int));
    embed_kernel<<<(n * 32 + 255) / 256, 256>>>(node_type, emb, xhiA, xloA, n);
    {
        const int TOT = L_LAY * D_DIM * KTOT;
        prep_kernel<<<(TOT + 255) / 256, 256>>>(W, root);
    }
    hist_kernel<<<(E + 255) / 256, 256>>>(edge_index, E);
    {
        const int nb = (n + 1023) / 1024;
        scanA_kernel<<<nb, 1024>>>(n);
        scanB_kernel<<<1, 64>>>(nb);
        scanC_kernel<<<(n + 1 + 1023) / 1024, 1024>>>(n, E);
    }
    reorder_kernel<<<(E + 255) / 256, 256>>>(edge_index, edge_type, E);

    const int agg_blocks  = (n * 32 + 255) / 256;
    const int gemm_blocks = (n + 127) / 128;

    for (int l = 0; l < L_LAY; l++) {
        const __nv_bfloat16* xih = (l == 1) ? xhiB : xhiA;
        const __nv_bfloat16* xil = (l == 1) ? xloB : xloA;
        __nv_bfloat16* xoh = (l == 0) ? xhiB : xhiA;
        __nv_bfloat16* xol = (l == 0) ? xloB : xloA;

        agg_kernel<<<agg_blocks, 256>>>(xih, xil, hhi, hlo, n);

        if (l < L_LAY - 1) {
            gemm_mma_kernel<<<gemm_blocks, 256, SM_TOTAL>>>(
                xih, xil, hhi, hlo,
                bhi + (size_t)l * D_DIM * KTOT,
                blo + (size_t)l * D_DIM * KTOT,
                bias + (size_t)l * D_DIM,
                xoh, xol, (float*)nullptr, n);
        } else {
            gemm_mma_kernel<<<gemm_blocks, 256, SM_TOTAL>>>(
                xih, xil, hhi, hlo,
                bhi + (size_t)l * D_DIM * KTOT,
                blo + (size_t)l * D_DIM * KTOT,
                bias + (size_t)l * D_DIM,
                (__nv_bfloat16*)nullptr, (__nv_bfloat16*)nullptr, out, n);
        }
    }
}